// round 11
// baseline (speedup 1.0000x reference)
#include <cuda_runtime.h>
#include <cuda_fp16.h>
#include <cstdint>

// Problem constants
#define M_DIM 4096
#define K_DIM 4096
#define N_DIM 11008

// GEMM tiling
#define BM 128
#define BN 128
#define BK 64                 // 64 halfs = 128B rows (8 x 16B chunks)
#define NTHREADS 128          // 4 warps: 2 along M x 2 along N; warp tile 64x64
#define NSTAGE 3

#define A_STAGE_BYTES (BM * 128)                       // 16384
#define B_STAGE_BYTES (BN * 128)                       // 16384
#define STAGE_BYTES   (A_STAGE_BYTES + B_STAGE_BYTES)  // 32768
#define SMEM_TOTAL    (NSTAGE * STAGE_BYTES)           // 98304

// Scratch (device globals; no cudaMalloc allowed)
__device__ __half g_X[(size_t)M_DIM * K_DIM];   // 32 MB  (x * scale, fp16)
__device__ __half g_W[(size_t)N_DIM * K_DIM];   // 90 MB  (exact int4 values)
__device__ float  g_c[M_DIM];

// ---------------------------------------------------------------------------
// Helpers
// ---------------------------------------------------------------------------
__device__ __forceinline__ uint32_t smem_u32(const void* p) {
    return (uint32_t)__cvta_generic_to_shared(p);
}
__device__ __forceinline__ void cp16(uint32_t s, const void* g) {
    asm volatile("cp.async.cg.shared.global [%0], [%1], 16;\n" :: "r"(s), "l"(g));
}
__device__ __forceinline__ void cp_commit() {
    asm volatile("cp.async.commit_group;\n");
}
template <int N>
__device__ __forceinline__ void cp_wait() {
    asm volatile("cp.async.wait_group %0;\n" :: "n"(N));
}
__device__ __forceinline__ void ldsm4(uint32_t* r, uint32_t addr) {
    asm volatile("ldmatrix.sync.aligned.m8n8.x4.shared.b16 {%0,%1,%2,%3}, [%4];\n"
        : "=r"(r[0]), "=r"(r[1]), "=r"(r[2]), "=r"(r[3]) : "r"(addr));
}
__device__ __forceinline__ void mma16816(float* d, const uint32_t* a, uint32_t b0, uint32_t b1) {
    asm volatile(
        "mma.sync.aligned.m16n8k16.row.col.f32.f16.f16.f32 "
        "{%0,%1,%2,%3},{%4,%5,%6,%7},{%8,%9},{%0,%1,%2,%3};\n"
        : "+f"(d[0]), "+f"(d[1]), "+f"(d[2]), "+f"(d[3])
        : "r"(a[0]), "r"(a[1]), "r"(a[2]), "r"(a[3]), "r"(b0), "r"(b1));
}

// ---------------------------------------------------------------------------
// Merged prep kernel:
//   blocks [0, M_DIM):   X' = x*s[g] (fp16, float4 path), c[m] reduction
//   blocks [M_DIM, ...): unpack int4 (one packed byte per int32) to fp16 W
// ---------------------------------------------------------------------------
#define W_PACK_TOTAL ((size_t)N_DIM * (K_DIM / 2))       // int32 count (1 byte each)
#define W_VEC_TOTAL  (W_PACK_TOTAL / 4)                  // int4 groups of 4 values
#define W_BLOCKS     ((unsigned)((W_VEC_TOTAL + 255) / 256))

__global__ void prep_kernel(const float* __restrict__ x,
                            const int*   __restrict__ pw,
                            const float* __restrict__ scales,
                            const float* __restrict__ zps) {
    if (blockIdx.x < M_DIM) {
        const int m = blockIdx.x;
        const float4* xr = reinterpret_cast<const float4*>(x + (size_t)m * K_DIM);
        __half2* xo = reinterpret_cast<__half2*>(g_X + (size_t)m * K_DIM);
        float csum = 0.f;
#pragma unroll
        for (int it = 0; it < 4; it++) {
            int q = threadIdx.x + it * 256;          // float4 index; k = 4q
            int gi = q >> 4;                         // (4q)>>6; all 4 share gi
            float s = __ldg(scales + gi);
            float z = __ldg(zps + gi);
            float4 v = xr[q];
            float a0 = v.x * s, a1 = v.y * s, a2 = v.z * s, a3 = v.w * s;
            xo[q * 2 + 0] = __floats2half2_rn(a0, a1);
            xo[q * 2 + 1] = __floats2half2_rn(a2, a3);
            csum += (a0 + a1 + a2 + a3) * z;
        }
        __shared__ float red[256];
        red[threadIdx.x] = csum;
        __syncthreads();
        for (int s = 128; s > 0; s >>= 1) {
            if (threadIdx.x < s) red[threadIdx.x] += red[threadIdx.x + s];
            __syncthreads();
        }
        if (threadIdx.x == 0) g_c[m] = red[0];
    } else {
        // Each int32 of pw holds ONE packed byte (two int4 nibbles).
        size_t i = (size_t)(blockIdx.x - M_DIM) * blockDim.x + threadIdx.x;
        if (i >= W_VEC_TOTAL) return;
        int4 v4 = reinterpret_cast<const int4*>(pw)[i];
        const uint32_t bias2 = 0x64086408u;          // half2(1032, 1032)
        int vv[4] = {v4.x, v4.y, v4.z, v4.w};
        uint32_t h[4];
#pragma unroll
        for (int j = 0; j < 4; j++) {
            uint32_t byte = (uint32_t)vv[j] & 0xFFu;
            // lo nibble (even k) -> low half, hi nibble (odd k) -> high half
            uint32_t pair = (byte & 0xFu) | ((byte & 0xF0u) << 12);
            pair = (pair ^ 0x00080008u) | 0x64006400u;   // half(1024 + ((v+8)&15))
            __half2 r = __hsub2(*reinterpret_cast<__half2*>(&pair),
                                *reinterpret_cast<const __half2*>(&bias2));
            h[j] = *reinterpret_cast<uint32_t*>(&r);
        }
        reinterpret_cast<uint4*>(g_W)[i] = make_uint4(h[0], h[1], h[2], h[3]);
    }
}

// ---------------------------------------------------------------------------
// GEMM: out[m,n] = X'[m,:] . W[n,:] - c[m] + bias[n]
// 128x128x64 block tile, 4 warps (2x2), warp tile 64x64, m16n8k16 fp16 mma,
// 3-stage cp.async pipeline, 2 CTAs/SM, XOR-swizzled 128B-row smem,
// hoisted swizzle bases, B-fragment double buffering, cp.async spread over kk.
// Rationale: 64x64 warp tile cuts smem fragment reads from 192 to 128 B/mma,
// desaturating the crossbar (was co-limiting with the HMMA pipe).
// ---------------------------------------------------------------------------
__global__ void __launch_bounds__(NTHREADS, 2)
gemm_kernel(const float* __restrict__ bias, float* __restrict__ out) {
    extern __shared__ __align__(1024) char smem_raw[];
    const uint32_t sbase = smem_u32(smem_raw);

    const int tid  = threadIdx.x;
    const int lane = tid & 31;
    const int warp = tid >> 5;
    const int wm = warp & 1;   // 0..1 along M (64 rows each)
    const int wn = warp >> 1;  // 0..1 along N (64 cols each)

    const int m0 = blockIdx.x * BM;
    const int n0 = blockIdx.y * BN;

    float acc[4][8][4];
#pragma unroll
    for (int i = 0; i < 4; i++)
#pragma unroll
        for (int j = 0; j < 8; j++)
#pragma unroll
            for (int v = 0; v < 4; v++) acc[i][j][v] = 0.f;

    const int NK = K_DIM / BK;  // 64

    // ---- hoisted ldsm swizzle bases (within-stage offsets) ----
    const int lrow  = lane & 15;
    const int lcsel = lane >> 4;
    uint32_t offA[4], offB[4];
#pragma unroll
    for (int mt = 0; mt < 4; mt++) {
        int row = wm * 64 + mt * 16 + lrow;
        offA[mt] = (uint32_t)(row * 128 + ((lcsel ^ (row & 7)) << 4));
    }
#pragma unroll
    for (int np = 0; np < 4; np++) {
        int row = wn * 64 + np * 16 + lrow;
        offB[np] = (uint32_t)(A_STAGE_BYTES + row * 128 + ((lcsel ^ (row & 7)) << 4));
    }

    // ---- hoisted loader state ----
    const int ldrow = tid >> 3;         // 0..15 (plus i*16)
    const int ldc   = tid & 7;          // 16B chunk within 128B row
    const char* pA = (const char*)(g_X + (size_t)(m0 + ldrow) * K_DIM) + ldc * 16;
    const char* pB = (const char*)(g_W + (size_t)(n0 + ldrow) * K_DIM) + ldc * 16;
    const uint32_t sOff = (uint32_t)(ldrow * 128 + ((ldc ^ (ldrow & 7)) << 4));
    const size_t GROWSTRIDE = (size_t)16 * K_DIM * 2;  // 16 rows in bytes

    // full-stage loader (prologue): 8 A + 8 B chunks per thread
#define LOAD_STAGE(S)                                                              \
    {                                                                              \
        uint32_t _s = sbase + (S) * STAGE_BYTES + sOff;                            \
        _Pragma("unroll")                                                          \
        for (int i = 0; i < 8; i++) {                                              \
            cp16(_s + i * 2048, pA + i * GROWSTRIDE);                              \
            cp16(_s + A_STAGE_BYTES + i * 2048, pB + i * GROWSTRIDE);              \
        }                                                                          \
        pA += 128; pB += 128;                                                      \
    }

    LOAD_STAGE(0);
    cp_commit();
    LOAD_STAGE(1);
    cp_commit();

    int ldst = 2;   // next stage to fill
    int cst  = 0;   // stage to compute

    for (int kt = 0; kt < NK; kt++) {
        cp_wait<1>();
        __syncthreads();

        const bool doLoad = (kt + 2 < NK);
        const uint32_t sT = sbase + cst * STAGE_BYTES;
        cst = (cst == NSTAGE - 1) ? 0 : cst + 1;
        const uint32_t sL = sbase + ldst * STAGE_BYTES + sOff;
        if (doLoad) ldst = (ldst == NSTAGE - 1) ? 0 : ldst + 1;

        // B fragment double buffer: preload kk=0
        uint32_t bb[2][4][4];
#pragma unroll
        for (int np = 0; np < 4; np++) ldsm4(bb[0][np], sT + offB[np]);

#pragma unroll
        for (int kk = 0; kk < 4; kk++) {      // 4 x K=16 steps per BK=64
            const uint32_t kx = (uint32_t)(kk << 5);
            const int cur = kk & 1;
            uint32_t ah[4][4];
            // A fragments for this kk (critical path: issue first)
#pragma unroll
            for (int mt = 0; mt < 4; mt++) ldsm4(ah[mt], sT + (offA[mt] ^ kx));
            // prefetch B fragments for kk+1
            if (kk < 3) {
                const uint32_t kx2 = (uint32_t)((kk + 1) << 5);
#pragma unroll
                for (int np = 0; np < 4; np++)
                    ldsm4(bb[cur ^ 1][np], sT + (offB[np] ^ kx2));
            }
            // spread stage-fill: 4 of 16 cp.async per kk
            if (doLoad) {
                cp16(sL + (2 * kk) * 2048, pA + (2 * kk) * GROWSTRIDE);
                cp16(sL + (2 * kk + 1) * 2048, pA + (2 * kk + 1) * GROWSTRIDE);
                cp16(sL + A_STAGE_BYTES + (2 * kk) * 2048, pB + (2 * kk) * GROWSTRIDE);
                cp16(sL + A_STAGE_BYTES + (2 * kk + 1) * 2048, pB + (2 * kk + 1) * GROWSTRIDE);
            }
#pragma unroll
            for (int mt = 0; mt < 4; mt++) {
#pragma unroll
                for (int nt = 0; nt < 8; nt++) {
                    uint32_t b0 = bb[cur][nt >> 1][nt & 1];
                    uint32_t b1 = bb[cur][nt >> 1][2 + (nt & 1)];
                    mma16816(acc[mt][nt], ah[mt], b0, b1);
                }
            }
        }
        if (doLoad) { pA += 128; pB += 128; }
        cp_commit();   // one group per iteration keeps wait counts aligned
    }

    // ---- epilogue: + bias[n] - c[m] ----
    const int g  = lane >> 2;
    const int tg = lane & 3;
#pragma unroll
    for (int mt = 0; mt < 4; mt++) {
        int row0 = m0 + wm * 64 + mt * 16 + g;
        int row1 = row0 + 8;
        float c0 = g_c[row0];
        float c1 = g_c[row1];
#pragma unroll
        for (int nt = 0; nt < 8; nt++) {
            int col = n0 + wn * 64 + nt * 8 + tg * 2;
            float2 bv = *reinterpret_cast<const float2*>(bias + col);
            float2 v0, v1;
            v0.x = acc[mt][nt][0] + bv.x - c0;
            v0.y = acc[mt][nt][1] + bv.y - c0;
            v1.x = acc[mt][nt][2] + bv.x - c1;
            v1.y = acc[mt][nt][3] + bv.y - c1;
            *reinterpret_cast<float2*>(out + (size_t)row0 * N_DIM + col) = v0;
            *reinterpret_cast<float2*>(out + (size_t)row1 * N_DIM + col) = v1;
        }
    }
#undef LOAD_STAGE
}

// ---------------------------------------------------------------------------
// Launch
// ---------------------------------------------------------------------------
extern "C" void kernel_launch(void* const* d_in, const int* in_sizes, int n_in,
                              void* d_out, int out_size) {
    const float* x    = (const float*)d_in[0];
    const int*   pw   = (const int*)d_in[1];
    const float* sc   = (const float*)d_in[2];
    const float* zp   = (const float*)d_in[3];
    const float* bias = (const float*)d_in[4];
    float* out = (float*)d_out;

    prep_kernel<<<M_DIM + W_BLOCKS, 256>>>(x, pw, sc, zp);

    cudaFuncSetAttribute(gemm_kernel,
                         cudaFuncAttributeMaxDynamicSharedMemorySize, SMEM_TOTAL);
    dim3 grid(M_DIM / BM, N_DIM / BN);  // (32, 86)
    gemm_kernel<<<grid, NTHREADS, SMEM_TOTAL>>>(bias, out);
}

// round 12
// speedup vs baseline: 1.0299x; 1.0299x over previous
#include <cuda_runtime.h>
#include <cuda_fp16.h>
#include <cstdint>

// Problem constants
#define M_DIM 4096
#define K_DIM 4096
#define N_DIM 11008

// GEMM tiling
#define BM 128
#define BN 128
#define BK 64                 // 64 halfs = 128B rows (8 x 16B chunks)
#define NTHREADS 256          // 8 warps: 2 along M x 4 along N; warp tile 64x32
#define NSTAGE 3

#define A_STAGE_BYTES (BM * 128)                       // 16384
#define B_STAGE_BYTES (BN * 128)                       // 16384
#define STAGE_BYTES   (A_STAGE_BYTES + B_STAGE_BYTES)  // 32768
#define SMEM_TOTAL    (NSTAGE * STAGE_BYTES)           // 98304

// Scratch (device globals; no cudaMalloc allowed)
__device__ __half g_X[(size_t)M_DIM * K_DIM];   // 32 MB  (x * scale, fp16)
__device__ __half g_W[(size_t)N_DIM * K_DIM];   // 90 MB  (exact int4 values)
__device__ float  g_c[M_DIM];

// ---------------------------------------------------------------------------
// Helpers
// ---------------------------------------------------------------------------
__device__ __forceinline__ uint32_t smem_u32(const void* p) {
    return (uint32_t)__cvta_generic_to_shared(p);
}
__device__ __forceinline__ void cp16(uint32_t s, const void* g) {
    asm volatile("cp.async.cg.shared.global [%0], [%1], 16;\n" :: "r"(s), "l"(g));
}
__device__ __forceinline__ void cp_commit() {
    asm volatile("cp.async.commit_group;\n");
}
template <int N>
__device__ __forceinline__ void cp_wait() {
    asm volatile("cp.async.wait_group %0;\n" :: "n"(N));
}
__device__ __forceinline__ void ldsm4(uint32_t* r, uint32_t addr) {
    asm volatile("ldmatrix.sync.aligned.m8n8.x4.shared.b16 {%0,%1,%2,%3}, [%4];\n"
        : "=r"(r[0]), "=r"(r[1]), "=r"(r[2]), "=r"(r[3]) : "r"(addr));
}
__device__ __forceinline__ void mma16816(float* d, const uint32_t* a, uint32_t b0, uint32_t b1) {
    asm volatile(
        "mma.sync.aligned.m16n8k16.row.col.f32.f16.f16.f32 "
        "{%0,%1,%2,%3},{%4,%5,%6,%7},{%8,%9},{%0,%1,%2,%3};\n"
        : "+f"(d[0]), "+f"(d[1]), "+f"(d[2]), "+f"(d[3])
        : "r"(a[0]), "r"(a[1]), "r"(a[2]), "r"(a[3]), "r"(b0), "r"(b1));
}

// ---------------------------------------------------------------------------
// Merged prep kernel:
//   blocks [0, M_DIM):   X' = x*s[g] (fp16, float4 path), c[m] reduction
//   blocks [M_DIM, ...): unpack int4 (one packed byte per int32) to fp16 W
// ---------------------------------------------------------------------------
#define W_PACK_TOTAL ((size_t)N_DIM * (K_DIM / 2))       // int32 count (1 byte each)
#define W_VEC_TOTAL  (W_PACK_TOTAL / 4)                  // int4 groups of 4 values
#define W_BLOCKS     ((unsigned)((W_VEC_TOTAL + 255) / 256))

__global__ void prep_kernel(const float* __restrict__ x,
                            const int*   __restrict__ pw,
                            const float* __restrict__ scales,
                            const float* __restrict__ zps) {
    if (blockIdx.x < M_DIM) {
        const int m = blockIdx.x;
        const float4* xr = reinterpret_cast<const float4*>(x + (size_t)m * K_DIM);
        __half2* xo = reinterpret_cast<__half2*>(g_X + (size_t)m * K_DIM);
        float csum = 0.f;
#pragma unroll
        for (int it = 0; it < 4; it++) {
            int q = threadIdx.x + it * 256;          // float4 index; k = 4q
            int gi = q >> 4;                         // (4q)>>6; all 4 share gi
            float s = __ldg(scales + gi);
            float z = __ldg(zps + gi);
            float4 v = xr[q];
            float a0 = v.x * s, a1 = v.y * s, a2 = v.z * s, a3 = v.w * s;
            xo[q * 2 + 0] = __floats2half2_rn(a0, a1);
            xo[q * 2 + 1] = __floats2half2_rn(a2, a3);
            csum += (a0 + a1 + a2 + a3) * z;
        }
        __shared__ float red[256];
        red[threadIdx.x] = csum;
        __syncthreads();
        for (int s = 128; s > 0; s >>= 1) {
            if (threadIdx.x < s) red[threadIdx.x] += red[threadIdx.x + s];
            __syncthreads();
        }
        if (threadIdx.x == 0) g_c[m] = red[0];
    } else {
        // Each int32 of pw holds ONE packed byte (two int4 nibbles).
        size_t i = (size_t)(blockIdx.x - M_DIM) * blockDim.x + threadIdx.x;
        if (i >= W_VEC_TOTAL) return;
        int4 v4 = reinterpret_cast<const int4*>(pw)[i];
        const uint32_t bias2 = 0x64086408u;          // half2(1032, 1032)
        int vv[4] = {v4.x, v4.y, v4.z, v4.w};
        uint32_t h[4];
#pragma unroll
        for (int j = 0; j < 4; j++) {
            uint32_t byte = (uint32_t)vv[j] & 0xFFu;
            // lo nibble (even k) -> low half, hi nibble (odd k) -> high half
            uint32_t pair = (byte & 0xFu) | ((byte & 0xF0u) << 12);
            pair = (pair ^ 0x00080008u) | 0x64006400u;   // half(1024 + ((v+8)&15))
            __half2 r = __hsub2(*reinterpret_cast<__half2*>(&pair),
                                *reinterpret_cast<const __half2*>(&bias2));
            h[j] = *reinterpret_cast<uint32_t*>(&r);
        }
        reinterpret_cast<uint4*>(g_W)[i] = make_uint4(h[0], h[1], h[2], h[3]);
    }
}

// ---------------------------------------------------------------------------
// GEMM: out[m,n] = X'[m,:] . W[n,:] - c[m] + bias[n]
// 128x128x64 block tile, 8 warps (2x4), warp tile 64x32, m16n8k16 fp16 mma,
// 3-stage cp.async pipeline, 2 CTAs/SM, XOR-swizzled 128B-row smem,
// hoisted swizzle bases, B-fragment double buffering, cp.async spread over kk.
// kt loop unrolled by 3 so all stage bases are compile-time constants.
// ---------------------------------------------------------------------------
__global__ void __launch_bounds__(NTHREADS, 2)
gemm_kernel(const float* __restrict__ bias, float* __restrict__ out) {
    extern __shared__ __align__(1024) char smem_raw[];
    const uint32_t sbase = smem_u32(smem_raw);

    const int tid  = threadIdx.x;
    const int lane = tid & 31;
    const int warp = tid >> 5;
    const int wm = warp & 1;   // 0..1 along M (64 rows each)
    const int wn = warp >> 1;  // 0..3 along N (32 cols each)

    const int m0 = blockIdx.x * BM;
    const int n0 = blockIdx.y * BN;

    float acc[4][4][4];
#pragma unroll
    for (int i = 0; i < 4; i++)
#pragma unroll
        for (int j = 0; j < 4; j++)
#pragma unroll
            for (int v = 0; v < 4; v++) acc[i][j][v] = 0.f;

    const int NK = K_DIM / BK;  // 64

    // ---- hoisted ldsm swizzle bases (within-stage offsets) ----
    const int lrow  = lane & 15;
    const int lcsel = lane >> 4;
    uint32_t offA[4], offB[2];
#pragma unroll
    for (int mt = 0; mt < 4; mt++) {
        int row = wm * 64 + mt * 16 + lrow;
        offA[mt] = (uint32_t)(row * 128 + ((lcsel ^ (row & 7)) << 4));
    }
#pragma unroll
    for (int np = 0; np < 2; np++) {
        int row = wn * 32 + np * 16 + lrow;
        offB[np] = (uint32_t)(A_STAGE_BYTES + row * 128 + ((lcsel ^ (row & 7)) << 4));
    }

    // ---- hoisted loader state ----
    const int ldrow = tid >> 3;         // 0..31 (plus i*32)
    const int ldc   = tid & 7;          // 16B chunk within 128B row
    const char* pA = (const char*)(g_X + (size_t)(m0 + ldrow) * K_DIM) + ldc * 16;
    const char* pB = (const char*)(g_W + (size_t)(n0 + ldrow) * K_DIM) + ldc * 16;
    const uint32_t sOff = (uint32_t)(ldrow * 128 + ((ldc ^ (ldrow & 7)) << 4));
    const size_t GROWSTRIDE = (size_t)32 * K_DIM * 2;  // 32 rows in bytes

    // full-stage loader used for the prologue only
#define LOAD_STAGE(S)                                                              \
    {                                                                              \
        uint32_t _s = sbase + (S) * STAGE_BYTES + sOff;                            \
        _Pragma("unroll")                                                          \
        for (int i = 0; i < 4; i++) {                                              \
            cp16(_s + i * 4096, pA + i * GROWSTRIDE);                              \
            cp16(_s + A_STAGE_BYTES + i * 4096, pB + i * GROWSTRIDE);              \
        }                                                                          \
        pA += 128; pB += 128;                                                      \
    }

    // kt body: CST/LST are compile-time stage indices after unroll
#define KT_BODY(CST, LST, DOLOAD)                                                  \
    {                                                                              \
        cp_wait<1>();                                                              \
        __syncthreads();                                                           \
        const uint32_t sT = sbase + (CST) * STAGE_BYTES;                           \
        const uint32_t sL = sbase + (LST) * STAGE_BYTES + sOff;                    \
        uint32_t bb[2][2][4];                                                      \
        ldsm4(bb[0][0], sT + offB[0]);                                             \
        ldsm4(bb[0][1], sT + offB[1]);                                             \
        _Pragma("unroll")                                                          \
        for (int kk = 0; kk < 4; kk++) {                                           \
            const uint32_t kx = (uint32_t)(kk << 5);                               \
            const int cur = kk & 1;                                                \
            uint32_t ah[4][4];                                                     \
            _Pragma("unroll")                                                      \
            for (int mt = 0; mt < 4; mt++) ldsm4(ah[mt], sT + (offA[mt] ^ kx));    \
            if (kk < 3) {                                                          \
                const uint32_t kx2 = (uint32_t)((kk + 1) << 5);                    \
                ldsm4(bb[cur ^ 1][0], sT + (offB[0] ^ kx2));                       \
                ldsm4(bb[cur ^ 1][1], sT + (offB[1] ^ kx2));                       \
            }                                                                      \
            if (DOLOAD) {                                                          \
                cp16(sL + kk * 4096, pA + kk * GROWSTRIDE);                        \
                cp16(sL + A_STAGE_BYTES + kk * 4096, pB + kk * GROWSTRIDE);        \
            }                                                                      \
            _Pragma("unroll")                                                      \
            for (int mt = 0; mt < 4; mt++) {                                       \
                _Pragma("unroll")                                                  \
                for (int nt = 0; nt < 4; nt++) {                                   \
                    uint32_t b0 = bb[cur][nt >> 1][nt & 1];                        \
                    uint32_t b1 = bb[cur][nt >> 1][2 + (nt & 1)];                  \
                    mma16816(acc[mt][nt], ah[mt], b0, b1);                         \
                }                                                                  \
            }                                                                      \
        }                                                                          \
        if (DOLOAD) { pA += 128; pB += 128; }                                      \
        cp_commit();                                                               \
    }

    LOAD_STAGE(0);
    cp_commit();
    LOAD_STAGE(1);
    cp_commit();

    // kt = 0..62 in 21 macro-iterations of 3; kt starts at multiple of 3, so
    // cst = s and ldst = (s+2)%3 are compile-time per sub-iteration.
    for (int kt0 = 0; kt0 < NK - 1; kt0 += 3) {
        const bool d0 = (kt0 + 2 < NK);
        const bool d1 = (kt0 + 3 < NK);
        const bool d2 = (kt0 + 4 < NK);
        KT_BODY(0, 2, d0);
        KT_BODY(1, 0, d1);
        KT_BODY(2, 1, d2);
    }
    // tail kt = 63 (stage 0, no load)
    KT_BODY(0, 2, false);

    // ---- epilogue: + bias[n] - c[m] ----
    const int g  = lane >> 2;
    const int tg = lane & 3;
#pragma unroll
    for (int mt = 0; mt < 4; mt++) {
        int row0 = m0 + wm * 64 + mt * 16 + g;
        int row1 = row0 + 8;
        float c0 = g_c[row0];
        float c1 = g_c[row1];
#pragma unroll
        for (int nt = 0; nt < 4; nt++) {
            int col = n0 + wn * 32 + nt * 8 + tg * 2;
            float2 bv = *reinterpret_cast<const float2*>(bias + col);
            float2 v0, v1;
            v0.x = acc[mt][nt][0] + bv.x - c0;
            v0.y = acc[mt][nt][1] + bv.y - c0;
            v1.x = acc[mt][nt][2] + bv.x - c1;
            v1.y = acc[mt][nt][3] + bv.y - c1;
            *reinterpret_cast<float2*>(out + (size_t)row0 * N_DIM + col) = v0;
            *reinterpret_cast<float2*>(out + (size_t)row1 * N_DIM + col) = v1;
        }
    }
#undef LOAD_STAGE
#undef KT_BODY
}

// ---------------------------------------------------------------------------
// Launch
// ---------------------------------------------------------------------------
extern "C" void kernel_launch(void* const* d_in, const int* in_sizes, int n_in,
                              void* d_out, int out_size) {
    const float* x    = (const float*)d_in[0];
    const int*   pw   = (const int*)d_in[1];
    const float* sc   = (const float*)d_in[2];
    const float* zp   = (const float*)d_in[3];
    const float* bias = (const float*)d_in[4];
    float* out = (float*)d_out;

    prep_kernel<<<M_DIM + W_BLOCKS, 256>>>(x, pw, sc, zp);

    cudaFuncSetAttribute(gemm_kernel,
                         cudaFuncAttributeMaxDynamicSharedMemorySize, SMEM_TOTAL);
    dim3 grid(M_DIM / BM, N_DIM / BN);  // (32, 86)
    gemm_kernel<<<grid, NTHREADS, SMEM_TOTAL>>>(bias, out);
}